// round 14
// baseline (speedup 1.0000x reference)
#include <cuda_runtime.h>
#include <cuda_fp16.h>
#include <math_constants.h>
#include <cstdint>

#define BLOCK 128
#define PTS   64

// ---- smem byte offsets (per block; 2 blocks/SM) ----
#define AHI_OFF   0         // act hi  [64][136] fp16 (stride 272B) = 17408
#define ALO_OFF   17408     // act lo
#define EHI_OFF   34816     // enc hi  [64][72] fp16 (stride 144B) = 9216
#define ELO_OFF   44032     // enc lo
#define B_OFF     53248     // weight buffer (single fp16 plane, max 200*128*2=51200)
#define WC1_OFF   104448    // Wc_1 fp32 [128][3]
#define BCOL_OFF  105984    // Wd2_3 col0 fp32 [128]
#define DENS_OFF  106496    // density fp32 [64]
#define PB_OFF    106752    // blend partials fp32 [2][64]
#define PR_OFF    107776    // rgb partials fp32 [2][64][3]
#define SMEM_BYTES 110848

#define SA 272
#define SE 144
#define ALO_DELTA 17408
#define ELO_DELTA 9216

// epilogue flag bits
#define F_RELU  1
#define F_STORE 2
#define F_DENS  4
#define F_BLEND 8
#define F_RGB   16

// ---- pre-converted weights: Bt[j][k] row-major, padded, single fp16 plane ----
__device__ __half g_w[143360];

__constant__ int c_loff[9] = {0, 9216, 26624, 44032, 69632, 87040, 104448, 121856, 143360};
__constant__ int c_kpad[8] = {72, 136, 136, 200, 136, 136, 136, 168};
__constant__ int c_n16[8]  = {1152, 2176, 2176, 3200, 2176, 2176, 2176, 2688};

__global__ void prepass_kernel(const float* __restrict__ Wd1_0, const float* __restrict__ Wd1_1,
                               const float* __restrict__ Wd1_2, const float* __restrict__ Wd2_0,
                               const float* __restrict__ Wd2_1, const float* __restrict__ Wd2_2,
                               const float* __restrict__ Wd2_3, const float* __restrict__ Wc_0) {
    int e = blockIdx.x * blockDim.x + threadIdx.x;
    if (e >= 143360) return;
    int l = 0;
    while (e >= c_loff[l + 1]) l++;
    int r = e - c_loff[l];
    int kp = c_kpad[l];
    int j = r / kp;
    int k = r % kp;
    float v = 0.f;
    switch (l) {
        case 0: if (k < 60) v = Wd1_0[k * 128 + j]; break;
        case 1: if (k < 128) v = Wd1_1[k * 128 + j]; break;
        case 2: if (k < 128) v = Wd1_2[k * 128 + j]; break;
        case 3: if (k < 60) v = Wd2_0[k * 128 + j];
                else if (k >= 64 && k < 192) v = Wd2_0[(k - 4) * 128 + j];
                break;
        case 4: if (k < 128) v = Wd2_1[k * 128 + j]; break;
        case 5: if (k < 128) v = Wd2_2[k * 128 + j]; break;
        case 6: if (k < 128) v = Wd2_3[k * 129 + (j + 1)]; break;  // rotated
        case 7: if (k < 24) v = Wc_0[k * 128 + j];
                else if (k >= 32 && k < 160) v = Wc_0[(k - 8) * 128 + j];
                break;
    }
    g_w[e] = __float2half_rn(v);
}

// ---- helpers ----
__device__ __forceinline__ void mma16816(float* d, const uint32_t* a, const uint32_t* b) {
    asm volatile(
        "mma.sync.aligned.m16n8k16.row.col.f32.f16.f16.f32 "
        "{%0,%1,%2,%3}, {%4,%5,%6,%7}, {%8,%9}, {%0,%1,%2,%3};"
        : "+f"(d[0]), "+f"(d[1]), "+f"(d[2]), "+f"(d[3])
        : "r"(a[0]), "r"(a[1]), "r"(a[2]), "r"(a[3]), "r"(b[0]), "r"(b[1]));
}

__device__ __forceinline__ void ldsm4(uint32_t* r, uint32_t addr) {
    asm volatile("ldmatrix.sync.aligned.m8n8.x4.shared.b16 {%0,%1,%2,%3}, [%4];"
                 : "=r"(r[0]), "=r"(r[1]), "=r"(r[2]), "=r"(r[3]) : "r"(addr));
}

__device__ __forceinline__ void cpasync16(uint32_t dst, const void* src) {
    asm volatile("cp.async.cg.shared.global [%0], [%1], 16;" :: "r"(dst), "l"(src));
}
#define CP_COMMIT() asm volatile("cp.async.commit_group;")
#define CP_WAIT0()  asm volatile("cp.async.wait_group 0;" ::: "memory")

__device__ __forceinline__ uint32_t smem_u32(const void* p) {
    uint32_t a;
    asm("{ .reg .u64 t; cvta.to.shared.u64 t, %1; cvt.u32.u64 %0, t; }" : "=r"(a) : "l"(p));
    return a;
}

__device__ __forceinline__ uint32_t packSplitHi(float f0, float f1, uint32_t& lp) {
    __half h0 = __float2half_rn(f0), h1 = __float2half_rn(f1);
    __half l0 = __float2half_rn(f0 - __half2float(h0));
    __half l1 = __float2half_rn(f1 - __half2float(h1));
    lp = ((uint32_t)__half_as_ushort(l1) << 16) | __half_as_ushort(l0);
    return ((uint32_t)__half_as_ushort(h1) << 16) | __half_as_ushort(h0);
}

__device__ __forceinline__ void encStore(char* sm, int row, int col, float f0, float f1) {
    uint32_t lp, hp = packSplitHi(f0, f1, lp);
    *reinterpret_cast<uint32_t*>(sm + EHI_OFF + row * SE + col * 2) = hp;
    *reinterpret_cast<uint32_t*>(sm + ELO_OFF + row * SE + col * 2) = lp;
}

__device__ __forceinline__ void copyB_async(uint32_t sb, int l) {
    const int n16 = c_n16[l];
    const char* src = reinterpret_cast<const char*>(g_w + c_loff[l]);
    const uint32_t dst = sb + B_OFF;
    for (int i = threadIdx.x; i < n16; i += BLOCK)
        cpasync16(dst + i * 16, src + i * 16);
    CP_COMMIT();
}

// One layer: EK enc k-tiles + AK act k-tiles, weight row stride SB bytes.
// 4 warps, warp tile 32 rows x 64 cols: wm = w&1 (rows 32wm..+31), wg = w>>1
// (cols 64wg..+63). 2-pass fp16: D = Ahi*B + Alo*B. 8 LDSM / 32 HMMA per kt.
// After the mid-barrier (all reads done) the next layer's copy starts.
template<int EK, int AK, int SB>
__device__ __noinline__ void layerT(char* sm, uint32_t sb, int flags, int nextL) {
    const int t = threadIdx.x;
    const int w = t >> 5, lane = t & 31;
    const int wm = w & 1, wg = w >> 1;
    const int q = lane & 3, rh = lane >> 2;
    const int arow = lane & 15, asel = lane >> 4;
    const int brow = (lane & 7) + ((lane >> 4) << 3);
    const int bsel = (lane >> 3) & 1;
    constexpr int TOT = EK + AK;

    const uint32_t aHi = sb + AHI_OFF + (uint32_t)(32 * wm + arow) * SA + asel * 16;
    const uint32_t eHi = sb + EHI_OFF + (uint32_t)(32 * wm + arow) * SE + asel * 16;
    const uint32_t bB0 = sb + B_OFF + (uint32_t)(brow + wg * 64) * SB + bsel * 16;

    float d[2][8][4];
#pragma unroll
    for (int mt = 0; mt < 2; mt++)
#pragma unroll
        for (int nt = 0; nt < 8; nt++) {
            d[mt][nt][0] = 0.f; d[mt][nt][1] = 0.f;
            d[mt][nt][2] = 0.f; d[mt][nt][3] = 0.f;
        }

#pragma unroll
    for (int kt = 0; kt < TOT; kt++) {
        uint32_t ah[2][4], al[2][4], bf[4][4];
        if (kt < EK) {
            ldsm4(ah[0], eHi + kt * 32);
            ldsm4(ah[1], eHi + 16 * SE + kt * 32);
            ldsm4(al[0], eHi + kt * 32 + ELO_DELTA);
            ldsm4(al[1], eHi + 16 * SE + kt * 32 + ELO_DELTA);
        } else {
            ldsm4(ah[0], aHi + (kt - EK) * 32);
            ldsm4(ah[1], aHi + 16 * SA + (kt - EK) * 32);
            ldsm4(al[0], aHi + (kt - EK) * 32 + ALO_DELTA);
            ldsm4(al[1], aHi + 16 * SA + (kt - EK) * 32 + ALO_DELTA);
        }
#pragma unroll
        for (int n4 = 0; n4 < 4; n4++)
            ldsm4(bf[n4], bB0 + kt * 32 + n4 * (16 * SB));
#pragma unroll
        for (int n4 = 0; n4 < 4; n4++)
#pragma unroll
            for (int mt = 0; mt < 2; mt++) {
                mma16816(d[mt][2 * n4],     ah[mt], bf[n4]);
                mma16816(d[mt][2 * n4 + 1], ah[mt], bf[n4] + 2);
            }
#pragma unroll
        for (int n4 = 0; n4 < 4; n4++)
#pragma unroll
            for (int mt = 0; mt < 2; mt++) {
                mma16816(d[mt][2 * n4],     al[mt], bf[n4]);
                mma16816(d[mt][2 * n4 + 1], al[mt], bf[n4] + 2);
            }
    }

    // ---- pre-barrier epilogue: relu (in place), aux partials, hi-pack ----
    const bool relu  = flags & F_RELU;
    const bool store = flags & F_STORE;
    const float* wc1  = reinterpret_cast<const float*>(sm + WC1_OFF);
    const float* bcol = reinterpret_cast<const float*>(sm + BCOL_OFF);
    uint32_t hpack[2][8][2];

#pragma unroll
    for (int mt = 0; mt < 2; mt++) {
        const int r0 = 32 * wm + 16 * mt + rh;
        if ((flags & F_DENS) && wg == 0 && q == 0) {
            reinterpret_cast<float*>(sm + DENS_OFF)[r0]     = d[mt][0][0];
            reinterpret_cast<float*>(sm + DENS_OFF)[r0 + 8] = d[mt][0][2];
        }
        float b0 = 0.f, b1 = 0.f;
        float g00 = 0.f, g01 = 0.f, g02 = 0.f, g10 = 0.f, g11 = 0.f, g12 = 0.f;
#pragma unroll
        for (int nt = 0; nt < 8; nt++) {
            float f00 = d[mt][nt][0], f01 = d[mt][nt][1];
            float f10 = d[mt][nt][2], f11 = d[mt][nt][3];
            if (relu) {
                f00 = fmaxf(f00, 0.f); f01 = fmaxf(f01, 0.f);
                f10 = fmaxf(f10, 0.f); f11 = fmaxf(f11, 0.f);
            }
            const int c = wg * 64 + nt * 8 + 2 * q;
            if (flags & F_BLEND) {
                b0 = fmaf(f00, bcol[c], fmaf(f01, bcol[c + 1], b0));
                b1 = fmaf(f10, bcol[c], fmaf(f11, bcol[c + 1], b1));
            }
            if (flags & F_RGB) {
                g00 = fmaf(f00, wc1[c * 3 + 0], fmaf(f01, wc1[(c + 1) * 3 + 0], g00));
                g01 = fmaf(f00, wc1[c * 3 + 1], fmaf(f01, wc1[(c + 1) * 3 + 1], g01));
                g02 = fmaf(f00, wc1[c * 3 + 2], fmaf(f01, wc1[(c + 1) * 3 + 2], g02));
                g10 = fmaf(f10, wc1[c * 3 + 0], fmaf(f11, wc1[(c + 1) * 3 + 0], g10));
                g11 = fmaf(f10, wc1[c * 3 + 1], fmaf(f11, wc1[(c + 1) * 3 + 1], g11));
                g12 = fmaf(f10, wc1[c * 3 + 2], fmaf(f11, wc1[(c + 1) * 3 + 2], g12));
            }
            if (store) {
                uint32_t lp0, lp1;
                hpack[mt][nt][0] = packSplitHi(f00, f01, lp0);
                hpack[mt][nt][1] = packSplitHi(f10, f11, lp1);
                d[mt][nt][0] = __uint_as_float(lp0);   // recycle dead accum regs
                d[mt][nt][1] = __uint_as_float(lp1);
            }
        }
        if (flags & F_BLEND) {
            b0 += __shfl_xor_sync(0xffffffffu, b0, 1);
            b0 += __shfl_xor_sync(0xffffffffu, b0, 2);
            b1 += __shfl_xor_sync(0xffffffffu, b1, 1);
            b1 += __shfl_xor_sync(0xffffffffu, b1, 2);
            if (q == 0) {
                reinterpret_cast<float*>(sm + PB_OFF)[wg * 64 + r0]     = b0;
                reinterpret_cast<float*>(sm + PB_OFF)[wg * 64 + r0 + 8] = b1;
            }
        }
        if (flags & F_RGB) {
            g00 += __shfl_xor_sync(0xffffffffu, g00, 1); g00 += __shfl_xor_sync(0xffffffffu, g00, 2);
            g01 += __shfl_xor_sync(0xffffffffu, g01, 1); g01 += __shfl_xor_sync(0xffffffffu, g01, 2);
            g02 += __shfl_xor_sync(0xffffffffu, g02, 1); g02 += __shfl_xor_sync(0xffffffffu, g02, 2);
            g10 += __shfl_xor_sync(0xffffffffu, g10, 1); g10 += __shfl_xor_sync(0xffffffffu, g10, 2);
            g11 += __shfl_xor_sync(0xffffffffu, g11, 1); g11 += __shfl_xor_sync(0xffffffffu, g11, 2);
            g12 += __shfl_xor_sync(0xffffffffu, g12, 1); g12 += __shfl_xor_sync(0xffffffffu, g12, 2);
            if (q == 0) {
                float* pr = reinterpret_cast<float*>(sm + PR_OFF) + (wg * 64) * 3;
                pr[r0 * 3 + 0] = g00; pr[r0 * 3 + 1] = g01; pr[r0 * 3 + 2] = g02;
                pr[(r0 + 8) * 3 + 0] = g10; pr[(r0 + 8) * 3 + 1] = g11; pr[(r0 + 8) * 3 + 2] = g12;
            }
        }
    }

    // All mainloop reads (act + B) complete block-wide.
    __syncthreads();

    // B buffer is now dead -> start next layer's weight copy under the stores.
    if (nextL >= 0) copyB_async(sb, nextL);

    if (store) {
#pragma unroll
        for (int mt = 0; mt < 2; mt++) {
            const int r0 = 32 * wm + 16 * mt + rh;
#pragma unroll
            for (int nt = 0; nt < 8; nt++) {
                char* p = sm + AHI_OFF + (uint32_t)r0 * SA + wg * 128 + nt * 16 + q * 4;
                *reinterpret_cast<uint32_t*>(p)                      = hpack[mt][nt][0];
                *reinterpret_cast<uint32_t*>(p + 8 * SA)             = hpack[mt][nt][1];
                *reinterpret_cast<uint32_t*>(p + ALO_DELTA)          = __float_as_uint(d[mt][nt][0]);
                *reinterpret_cast<uint32_t*>(p + ALO_DELTA + 8 * SA) = __float_as_uint(d[mt][nt][1]);
            }
        }
    }
}

__global__ void __launch_bounds__(BLOCK, 2)
nerf_mma_kernel(const float* __restrict__ x, const float* __restrict__ Wd2_3,
                const float* __restrict__ Wc_1, float* __restrict__ out, int N) {
    extern __shared__ char sm[];
    const uint32_t sb = smem_u32(sm);
    const int t = threadIdx.x;
    const int i0 = blockIdx.x * PTS;

    copyB_async(sb, 0);

    for (int idx = t; idx < 384; idx += BLOCK)
        reinterpret_cast<float*>(sm + WC1_OFF)[idx] = Wc_1[idx];
    if (t < 128) reinterpret_cast<float*>(sm + BCOL_OFF)[t] = Wd2_3[t * 129];

    float vx = 0.f, vy = 0.f, vz = 0.f;
    if (t < PTS) {
        int i = i0 + t;
        float p0 = 0.f, p1 = 0.f, p2 = 0.f;
        if (i < N) {
            const float* xp = x + 6 * i;
            p0 = xp[0]; p1 = xp[1]; p2 = xp[2];
            vx = xp[3]; vy = xp[4]; vz = xp[5];
        }
#pragma unroll
        for (int dd = 0; dd < 3; dd++) {
            float base = (dd == 0) ? p0 : ((dd == 1) ? p1 : p2);
#pragma unroll
            for (int f = 0; f < 10; f++) {
                float s, c;
                sincosf(base * (CUDART_PI_F * (float)(1 << f)), &s, &c);
                encStore(sm, t, dd * 20 + 2 * f, s, c);
            }
        }
        encStore(sm, t, 60, 0.f, 0.f);
        encStore(sm, t, 62, 0.f, 0.f);
    }

    CP_WAIT0(); __syncthreads();
    layerT<4, 0, 144>(sm, sb, F_RELU | F_STORE, 1);              // L1

    CP_WAIT0(); __syncthreads();
    layerT<0, 8, 272>(sm, sb, F_RELU | F_STORE, 2);              // L2

    CP_WAIT0(); __syncthreads();
    layerT<0, 8, 272>(sm, sb, F_STORE, 3);                       // L3 (linear)

    CP_WAIT0(); __syncthreads();
    layerT<4, 8, 400>(sm, sb, F_RELU | F_STORE, 4);              // L4

    // enc_pos reads finished at L4's mid-barrier -> write view enc now
    if (t < PTS) {
#pragma unroll
        for (int dd = 0; dd < 3; dd++) {
            float base = (dd == 0) ? vx : ((dd == 1) ? vy : vz);
#pragma unroll
            for (int f = 0; f < 4; f++) {
                float s, c;
                sincosf(base * (CUDART_PI_F * (float)(1 << f)), &s, &c);
                encStore(sm, t, dd * 8 + 2 * f, s, c);
            }
        }
        encStore(sm, t, 24, 0.f, 0.f);
        encStore(sm, t, 26, 0.f, 0.f);
        encStore(sm, t, 28, 0.f, 0.f);
        encStore(sm, t, 30, 0.f, 0.f);
    }

    CP_WAIT0(); __syncthreads();
    layerT<0, 8, 272>(sm, sb, F_RELU | F_STORE, 5);              // L5

    CP_WAIT0(); __syncthreads();
    layerT<0, 8, 272>(sm, sb, F_RELU | F_STORE | F_BLEND, 6);    // L6

    CP_WAIT0(); __syncthreads();
    layerT<0, 8, 272>(sm, sb, F_STORE | F_DENS, 7);              // L7 (linear)

    CP_WAIT0(); __syncthreads();
    layerT<2, 8, 336>(sm, sb, F_RELU | F_RGB, -1);               // L8

    __syncthreads();
    if (t < PTS) {
        int i = i0 + t;
        if (i < N) {
            const float* pr = reinterpret_cast<const float*>(sm + PR_OFF);
            const float* pb = reinterpret_cast<const float*>(sm + PB_OFF);
            float braw = pb[t] + pb[64 + t];
            float* o = out + 5 * i;
            o[0] = pr[t * 3 + 0] + pr[(64 + t) * 3 + 0];
            o[1] = pr[t * 3 + 1] + pr[(64 + t) * 3 + 1];
            o[2] = pr[t * 3 + 2] + pr[(64 + t) * 3 + 2];
            o[3] = reinterpret_cast<const float*>(sm + DENS_OFF)[t];
            o[4] = 1.f / (1.f + expf(-braw));
        }
    }
}

extern "C" void kernel_launch(void* const* d_in, const int* in_sizes, int n_in,
                              void* d_out, int out_size) {
    const float* x     = (const float*)d_in[0];
    const float* Wd1_0 = (const float*)d_in[1];
    const float* Wd1_1 = (const float*)d_in[2];
    const float* Wd1_2 = (const float*)d_in[3];
    const float* Wd2_0 = (const float*)d_in[4];
    const float* Wd2_1 = (const float*)d_in[5];
    const float* Wd2_2 = (const float*)d_in[6];
    const float* Wd2_3 = (const float*)d_in[7];
    const float* Wc_0  = (const float*)d_in[8];
    const float* Wc_1  = (const float*)d_in[9];
    float* out = (float*)d_out;

    int N = in_sizes[0] / 6;
    if (N <= 0) return;

    prepass_kernel<<<(143360 + 255) / 256, 256>>>(Wd1_0, Wd1_1, Wd1_2, Wd2_0,
                                                  Wd2_1, Wd2_2, Wd2_3, Wc_0);

    cudaFuncSetAttribute(nerf_mma_kernel,
                         cudaFuncAttributeMaxDynamicSharedMemorySize, SMEM_BYTES);
    int grid = (N + PTS - 1) / PTS;
    nerf_mma_kernel<<<grid, BLOCK, SMEM_BYTES>>>(x, Wd2_3, Wc_1, out, N);
}

// round 15
// speedup vs baseline: 1.7208x; 1.7208x over previous
#include <cuda_runtime.h>
#include <cuda_fp16.h>
#include <math_constants.h>
#include <cstdint>

#define BLOCK 256
#define PTS   64

// ---- smem byte offsets (per block; 2 blocks/SM) ----
#define AHI_OFF   0         // act fp16 [64][136] (stride 272B) = 17408
#define EHI_OFF   17408     // enc fp16 [64][72]  (stride 144B) = 9216
#define B_OFF     26624     // weight buffer (fp16, max 200*128*2=51200)
#define WC1_OFF   77824     // Wc_1 fp32 [128][3]
#define BCOL_OFF  79360     // Wd2_3 col0 fp32 [128]
#define DENS_OFF  79872     // density fp32 [64]
#define PB_OFF    80128     // blend partials fp32 [4][64]
#define PR_OFF    81152     // rgb partials fp32 [4][64][3]
#define SMEM_BYTES 84224

#define SA 272
#define SE 144

// epilogue flag bits
#define F_RELU  1
#define F_STORE 2
#define F_DENS  4
#define F_BLEND 8
#define F_RGB   16

// ---- pre-converted weights: Bt[j][k] row-major, padded, single fp16 plane ----
__device__ __half g_w[143360];

__constant__ int c_loff[9] = {0, 9216, 26624, 44032, 69632, 87040, 104448, 121856, 143360};
__constant__ int c_kpad[8] = {72, 136, 136, 200, 136, 136, 136, 168};
__constant__ int c_n16[8]  = {1152, 2176, 2176, 3200, 2176, 2176, 2176, 2688};

__global__ void prepass_kernel(const float* __restrict__ Wd1_0, const float* __restrict__ Wd1_1,
                               const float* __restrict__ Wd1_2, const float* __restrict__ Wd2_0,
                               const float* __restrict__ Wd2_1, const float* __restrict__ Wd2_2,
                               const float* __restrict__ Wd2_3, const float* __restrict__ Wc_0) {
    int e = blockIdx.x * blockDim.x + threadIdx.x;
    if (e >= 143360) return;
    int l = 0;
    while (e >= c_loff[l + 1]) l++;
    int r = e - c_loff[l];
    int kp = c_kpad[l];
    int j = r / kp;
    int k = r % kp;
    float v = 0.f;
    switch (l) {
        case 0: if (k < 60) v = Wd1_0[k * 128 + j]; break;
        case 1: if (k < 128) v = Wd1_1[k * 128 + j]; break;
        case 2: if (k < 128) v = Wd1_2[k * 128 + j]; break;
        case 3: if (k < 60) v = Wd2_0[k * 128 + j];
                else if (k >= 64 && k < 192) v = Wd2_0[(k - 4) * 128 + j];
                break;
        case 4: if (k < 128) v = Wd2_1[k * 128 + j]; break;
        case 5: if (k < 128) v = Wd2_2[k * 128 + j]; break;
        case 6: if (k < 128) v = Wd2_3[k * 129 + (j + 1)]; break;  // rotated
        case 7: if (k < 24) v = Wc_0[k * 128 + j];
                else if (k >= 32 && k < 160) v = Wc_0[(k - 8) * 128 + j];
                break;
    }
    g_w[e] = __float2half_rn(v);
}

// ---- helpers ----
__device__ __forceinline__ void mma16816(float* d, const uint32_t* a, const uint32_t* b) {
    asm volatile(
        "mma.sync.aligned.m16n8k16.row.col.f32.f16.f16.f32 "
        "{%0,%1,%2,%3}, {%4,%5,%6,%7}, {%8,%9}, {%0,%1,%2,%3};"
        : "+f"(d[0]), "+f"(d[1]), "+f"(d[2]), "+f"(d[3])
        : "r"(a[0]), "r"(a[1]), "r"(a[2]), "r"(a[3]), "r"(b[0]), "r"(b[1]));
}

__device__ __forceinline__ void ldsm4(uint32_t* r, uint32_t addr) {
    asm volatile("ldmatrix.sync.aligned.m8n8.x4.shared.b16 {%0,%1,%2,%3}, [%4];"
                 : "=r"(r[0]), "=r"(r[1]), "=r"(r[2]), "=r"(r[3]) : "r"(addr));
}

__device__ __forceinline__ void cpasync16(uint32_t dst, const void* src) {
    asm volatile("cp.async.cg.shared.global [%0], [%1], 16;" :: "r"(dst), "l"(src));
}
#define CP_COMMIT() asm volatile("cp.async.commit_group;")
#define CP_WAIT0()  asm volatile("cp.async.wait_group 0;" ::: "memory")

__device__ __forceinline__ uint32_t smem_u32(const void* p) {
    uint32_t a;
    asm("{ .reg .u64 t; cvta.to.shared.u64 t, %1; cvt.u32.u64 %0, t; }" : "=r"(a) : "l"(p));
    return a;
}

__device__ __forceinline__ uint32_t packHi(float f0, float f1) {
    __half h0 = __float2half_rn(f0), h1 = __float2half_rn(f1);
    return ((uint32_t)__half_as_ushort(h1) << 16) | __half_as_ushort(h0);
}

__device__ __forceinline__ void encStore(char* sm, int row, int col, float f0, float f1) {
    *reinterpret_cast<uint32_t*>(sm + EHI_OFF + row * SE + col * 2) = packHi(f0, f1);
}

__device__ __forceinline__ void copyB_async(uint32_t sb, int l) {
    const int n16 = c_n16[l];
    const char* src = reinterpret_cast<const char*>(g_w + c_loff[l]);
    const uint32_t dst = sb + B_OFF;
    for (int i = threadIdx.x; i < n16; i += BLOCK)
        cpasync16(dst + i * 16, src + i * 16);
    CP_COMMIT();
}

// One layer: EK enc k-tiles + AK act k-tiles, weight row stride SB bytes.
// 8 warps, warp tile 32 rows x 32 cols: wm = w&1 (rows 32wm..+31), wg = w>>1
// (cols 32wg..+31). 1-pass fp16: D = A*B (4 LDSM / 8 HMMA per kt).
// After the mid-barrier (all reads done), the next layer's weight copy starts.
template<int EK, int AK, int SB>
__device__ __noinline__ void layerT(char* sm, uint32_t sb, int flags, int nextL) {
    const int t = threadIdx.x;
    const int w = t >> 5, lane = t & 31;
    const int wm = w & 1, wg = w >> 1;
    const int q = lane & 3, rh = lane >> 2;
    const int arow = lane & 15, asel = lane >> 4;
    const int brow = (lane & 7) + ((lane >> 4) << 3);
    const int bsel = (lane >> 3) & 1;
    constexpr int TOT = EK + AK;

    const uint32_t aHi = sb + AHI_OFF + (uint32_t)(32 * wm + arow) * SA + asel * 16;
    const uint32_t eHi = sb + EHI_OFF + (uint32_t)(32 * wm + arow) * SE + asel * 16;
    const uint32_t bB0 = sb + B_OFF + (uint32_t)(brow + wg * 32) * SB + bsel * 16;

    float d[2][4][4];
#pragma unroll
    for (int mt = 0; mt < 2; mt++)
#pragma unroll
        for (int nt = 0; nt < 4; nt++) {
            d[mt][nt][0] = 0.f; d[mt][nt][1] = 0.f;
            d[mt][nt][2] = 0.f; d[mt][nt][3] = 0.f;
        }

#pragma unroll
    for (int kt = 0; kt < TOT; kt++) {
        uint32_t ah[2][4], bf[2][4];
        if (kt < EK) {
            ldsm4(ah[0], eHi + kt * 32);
            ldsm4(ah[1], eHi + 16 * SE + kt * 32);
        } else {
            ldsm4(ah[0], aHi + (kt - EK) * 32);
            ldsm4(ah[1], aHi + 16 * SA + (kt - EK) * 32);
        }
        ldsm4(bf[0], bB0 + kt * 32);
        ldsm4(bf[1], bB0 + kt * 32 + 16 * SB);
#pragma unroll
        for (int n2 = 0; n2 < 2; n2++)
#pragma unroll
            for (int mt = 0; mt < 2; mt++) {
                mma16816(d[mt][2 * n2],     ah[mt], bf[n2]);
                mma16816(d[mt][2 * n2 + 1], ah[mt], bf[n2] + 2);
            }
    }

    // ---- pre-barrier epilogue: relu, aux partials, pack into dead accum regs ----
    const bool relu  = flags & F_RELU;
    const bool store = flags & F_STORE;
    const float* wc1  = reinterpret_cast<const float*>(sm + WC1_OFF);
    const float* bcol = reinterpret_cast<const float*>(sm + BCOL_OFF);

#pragma unroll
    for (int mt = 0; mt < 2; mt++) {
        const int r0 = 32 * wm + 16 * mt + rh;
        if ((flags & F_DENS) && wg == 0 && q == 0) {
            reinterpret_cast<float*>(sm + DENS_OFF)[r0]     = d[mt][0][0];
            reinterpret_cast<float*>(sm + DENS_OFF)[r0 + 8] = d[mt][0][2];
        }
        float b0 = 0.f, b1 = 0.f;
        float g00 = 0.f, g01 = 0.f, g02 = 0.f, g10 = 0.f, g11 = 0.f, g12 = 0.f;
#pragma unroll
        for (int nt = 0; nt < 4; nt++) {
            float f00 = d[mt][nt][0], f01 = d[mt][nt][1];
            float f10 = d[mt][nt][2], f11 = d[mt][nt][3];
            if (relu) {
                f00 = fmaxf(f00, 0.f); f01 = fmaxf(f01, 0.f);
                f10 = fmaxf(f10, 0.f); f11 = fmaxf(f11, 0.f);
            }
            const int c = wg * 32 + nt * 8 + 2 * q;
            if (flags & F_BLEND) {
                b0 = fmaf(f00, bcol[c], fmaf(f01, bcol[c + 1], b0));
                b1 = fmaf(f10, bcol[c], fmaf(f11, bcol[c + 1], b1));
            }
            if (flags & F_RGB) {
                g00 = fmaf(f00, wc1[c * 3 + 0], fmaf(f01, wc1[(c + 1) * 3 + 0], g00));
                g01 = fmaf(f00, wc1[c * 3 + 1], fmaf(f01, wc1[(c + 1) * 3 + 1], g01));
                g02 = fmaf(f00, wc1[c * 3 + 2], fmaf(f01, wc1[(c + 1) * 3 + 2], g02));
                g10 = fmaf(f10, wc1[c * 3 + 0], fmaf(f11, wc1[(c + 1) * 3 + 0], g10));
                g11 = fmaf(f10, wc1[c * 3 + 1], fmaf(f11, wc1[(c + 1) * 3 + 1], g11));
                g12 = fmaf(f10, wc1[c * 3 + 2], fmaf(f11, wc1[(c + 1) * 3 + 2], g12));
            }
            if (store) {
                d[mt][nt][0] = __uint_as_float(packHi(f00, f01));  // row r0
                d[mt][nt][1] = __uint_as_float(packHi(f10, f11));  // row r0+8
            }
        }
        if (flags & F_BLEND) {
            b0 += __shfl_xor_sync(0xffffffffu, b0, 1);
            b0 += __shfl_xor_sync(0xffffffffu, b0, 2);
            b1 += __shfl_xor_sync(0xffffffffu, b1, 1);
            b1 += __shfl_xor_sync(0xffffffffu, b1, 2);
            if (q == 0) {
                reinterpret_cast<float*>(sm + PB_OFF)[wg * 64 + r0]     = b0;
                reinterpret_cast<float*>(sm + PB_OFF)[wg * 64 + r0 + 8] = b1;
            }
        }
        if (flags & F_RGB) {
            g00 += __shfl_xor_sync(0xffffffffu, g00, 1); g00 += __shfl_xor_sync(0xffffffffu, g00, 2);
            g01 += __shfl_xor_sync(0xffffffffu, g01, 1); g01 += __shfl_xor_sync(0xffffffffu, g01, 2);
            g02 += __shfl_xor_sync(0xffffffffu, g02, 1); g02 += __shfl_xor_sync(0xffffffffu, g02, 2);
            g10 += __shfl_xor_sync(0xffffffffu, g10, 1); g10 += __shfl_xor_sync(0xffffffffu, g10, 2);
            g11 += __shfl_xor_sync(0xffffffffu, g11, 1); g11 += __shfl_xor_sync(0xffffffffu, g11, 2);
            g12 += __shfl_xor_sync(0xffffffffu, g12, 1); g12 += __shfl_xor_sync(0xffffffffu, g12, 2);
            if (q == 0) {
                float* pr = reinterpret_cast<float*>(sm + PR_OFF) + (wg * 64) * 3;
                pr[r0 * 3 + 0] = g00; pr[r0 * 3 + 1] = g01; pr[r0 * 3 + 2] = g02;
                pr[(r0 + 8) * 3 + 0] = g10; pr[(r0 + 8) * 3 + 1] = g11; pr[(r0 + 8) * 3 + 2] = g12;
            }
        }
    }

    // All mainloop reads (act + enc + B) complete block-wide.
    __syncthreads();

    // B buffer is now dead -> start next layer's weight copy under the stores.
    if (nextL >= 0) copyB_async(sb, nextL);

    if (store) {
#pragma unroll
        for (int mt = 0; mt < 2; mt++) {
            const int r0 = 32 * wm + 16 * mt + rh;
#pragma unroll
            for (int nt = 0; nt < 4; nt++) {
                char* p = sm + AHI_OFF + (uint32_t)r0 * SA + wg * 64 + nt * 16 + q * 4;
                *reinterpret_cast<uint32_t*>(p)          = __float_as_uint(d[mt][nt][0]);
                *reinterpret_cast<uint32_t*>(p + 8 * SA) = __float_as_uint(d[mt][nt][1]);
            }
        }
    }
}

__global__ void __launch_bounds__(BLOCK, 2)
nerf_mma_kernel(const float* __restrict__ x, const float* __restrict__ Wd2_3,
                const float* __restrict__ Wc_1, float* __restrict__ out, int N) {
    extern __shared__ char sm[];
    const uint32_t sb = smem_u32(sm);
    const int t = threadIdx.x;
    const int i0 = blockIdx.x * PTS;

    copyB_async(sb, 0);

    for (int idx = t; idx < 384; idx += BLOCK)
        reinterpret_cast<float*>(sm + WC1_OFF)[idx] = Wc_1[idx];
    if (t < 128) reinterpret_cast<float*>(sm + BCOL_OFF)[t] = Wd2_3[t * 129];

    float vx = 0.f, vy = 0.f, vz = 0.f;
    if (t < PTS) {
        int i = i0 + t;
        float p0 = 0.f, p1 = 0.f, p2 = 0.f;
        if (i < N) {
            const float* xp = x + 6 * i;
            p0 = xp[0]; p1 = xp[1]; p2 = xp[2];
            vx = xp[3]; vy = xp[4]; vz = xp[5];
        }
#pragma unroll
        for (int dd = 0; dd < 3; dd++) {
            float base = (dd == 0) ? p0 : ((dd == 1) ? p1 : p2);
#pragma unroll
            for (int f = 0; f < 10; f++) {
                float s, c;
                sincosf(base * (CUDART_PI_F * (float)(1 << f)), &s, &c);
                encStore(sm, t, dd * 20 + 2 * f, s, c);
            }
        }
        encStore(sm, t, 60, 0.f, 0.f);
        encStore(sm, t, 62, 0.f, 0.f);
    }

    CP_WAIT0(); __syncthreads();
    layerT<4, 0, 144>(sm, sb, F_RELU | F_STORE, 1);              // L1

    CP_WAIT0(); __syncthreads();
    layerT<0, 8, 272>(sm, sb, F_RELU | F_STORE, 2);              // L2

    CP_WAIT0(); __syncthreads();
    layerT<0, 8, 272>(sm, sb, F_STORE, 3);                       // L3 (linear)

    CP_WAIT0(); __syncthreads();
    layerT<4, 8, 400>(sm, sb, F_RELU | F_STORE, 4);              // L4

    // enc_pos reads finished at L4's mid-barrier -> write view enc now
    if (t < PTS) {
#pragma unroll
        for (int dd = 0; dd < 3; dd++) {
            float base = (dd == 0) ? vx : ((dd == 1) ? vy : vz);
#pragma unroll
            for (int f = 0; f < 4; f++) {
                float s, c;
                sincosf(base * (CUDART_PI_F * (float)(1 << f)), &s, &c);
                encStore(sm, t, dd * 8 + 2 * f, s, c);
            }
        }
        encStore(sm, t, 24, 0.f, 0.f);
        encStore(sm, t, 26, 0.f, 0.f);
        encStore(sm, t, 28, 0.f, 0.f);
        encStore(sm, t, 30, 0.f, 0.f);
    }

    CP_WAIT0(); __syncthreads();
    layerT<0, 8, 272>(sm, sb, F_RELU | F_STORE, 5);              // L5

    CP_WAIT0(); __syncthreads();
    layerT<0, 8, 272>(sm, sb, F_RELU | F_STORE | F_BLEND, 6);    // L6

    CP_WAIT0(); __syncthreads();
    layerT<0, 8, 272>(sm, sb, F_STORE | F_DENS, 7);              // L7 (linear)

    CP_WAIT0(); __syncthreads();
    layerT<2, 8, 336>(sm, sb, F_RELU | F_RGB, -1);               // L8

    __syncthreads();
    if (t < PTS) {
        int i = i0 + t;
        if (i < N) {
            const float* pr = reinterpret_cast<const float*>(sm + PR_OFF);
            const float* pb = reinterpret_cast<const float*>(sm + PB_OFF);
            float braw = pb[t] + pb[64 + t] + pb[128 + t] + pb[192 + t];
            float r0 = 0.f, r1 = 0.f, r2 = 0.f;
#pragma unroll
            for (int g = 0; g < 4; g++) {
                r0 += pr[(g * 64 + t) * 3 + 0];
                r1 += pr[(g * 64 + t) * 3 + 1];
                r2 += pr[(g * 64 + t) * 3 + 2];
            }
            float* o = out + 5 * i;
            o[0] = r0;
            o[1] = r1;
            o[2] = r2;
            o[3] = reinterpret_cast<const float*>(sm + DENS_OFF)[t];
            o[4] = 1.f / (1.f + expf(-braw));
        }
    }
}

extern "C" void kernel_launch(void* const* d_in, const int* in_sizes, int n_in,
                              void* d_out, int out_size) {
    const float* x     = (const float*)d_in[0];
    const float* Wd1_0 = (const float*)d_in[1];
    const float* Wd1_1 = (const float*)d_in[2];
    const float* Wd1_2 = (const float*)d_in[3];
    const float* Wd2_0 = (const float*)d_in[4];
    const float* Wd2_1 = (const float*)d_in[5];
    const float* Wd2_2 = (const float*)d_in[6];
    const float* Wd2_3 = (const float*)d_in[7];
    const float* Wc_0  = (const float*)d_in[8];
    const float* Wc_1  = (const float*)d_in[9];
    float* out = (float*)d_out;

    int N = in_sizes[0] / 6;
    if (N <= 0) return;

    prepass_kernel<<<(143360 + 255) / 256, 256>>>(Wd1_0, Wd1_1, Wd1_2, Wd2_0,
                                                  Wd2_1, Wd2_2, Wd2_3, Wc_0);

    cudaFuncSetAttribute(nerf_mma_kernel,
                         cudaFuncAttributeMaxDynamicSharedMemorySize, SMEM_BYTES);
    int grid = (N + PTS - 1) / PTS;
    nerf_mma_kernel<<<grid, BLOCK, SMEM_BYTES>>>(x, Wd2_3, Wc_1, out, N);
}

// round 16
// speedup vs baseline: 2.1628x; 1.2569x over previous
#include <cuda_runtime.h>
#include <cuda_fp16.h>
#include <math_constants.h>
#include <cstdint>

#define BLOCK 256
#define PTS   128

// ---- smem byte offsets (per block; 2 blocks/SM) ----
#define AHI_OFF   0         // act fp16 [128][136] (stride 272B) = 34816
#define EHI_OFF   34816     // enc fp16 [128][72]  (stride 144B) = 18432
#define B_OFF     53248     // weight buffer (fp16, max 200*128*2=51200)
#define WC1_OFF   104448    // Wc_1 fp32 [128][3]
#define BCOL_OFF  105984    // Wd2_3 col0 fp32 [128]
#define DENS_OFF  106496    // density fp32 [128]
#define PB_OFF    107008    // blend partials fp32 [2][128]
#define PR_OFF    108032    // rgb partials fp32 [2][128][3]
#define SMEM_BYTES 111104

#define SA 272
#define SE 144

// epilogue flag bits
#define F_RELU  1
#define F_STORE 2
#define F_DENS  4
#define F_BLEND 8
#define F_RGB   16

// ---- pre-converted weights: Bt[j][k] row-major, padded, single fp16 plane ----
__device__ __half g_w[143360];

__constant__ int c_loff[9] = {0, 9216, 26624, 44032, 69632, 87040, 104448, 121856, 143360};
__constant__ int c_kpad[8] = {72, 136, 136, 200, 136, 136, 136, 168};
__constant__ int c_n16[8]  = {1152, 2176, 2176, 3200, 2176, 2176, 2176, 2688};

__global__ void prepass_kernel(const float* __restrict__ Wd1_0, const float* __restrict__ Wd1_1,
                               const float* __restrict__ Wd1_2, const float* __restrict__ Wd2_0,
                               const float* __restrict__ Wd2_1, const float* __restrict__ Wd2_2,
                               const float* __restrict__ Wd2_3, const float* __restrict__ Wc_0) {
    int e = blockIdx.x * blockDim.x + threadIdx.x;
    if (e >= 143360) return;
    int l = 0;
    while (e >= c_loff[l + 1]) l++;
    int r = e - c_loff[l];
    int kp = c_kpad[l];
    int j = r / kp;
    int k = r % kp;
    float v = 0.f;
    switch (l) {
        case 0: if (k < 60) v = Wd1_0[k * 128 + j]; break;
        case 1: if (k < 128) v = Wd1_1[k * 128 + j]; break;
        case 2: if (k < 128) v = Wd1_2[k * 128 + j]; break;
        case 3: if (k < 60) v = Wd2_0[k * 128 + j];
                else if (k >= 64 && k < 192) v = Wd2_0[(k - 4) * 128 + j];
                break;
        case 4: if (k < 128) v = Wd2_1[k * 128 + j]; break;
        case 5: if (k < 128) v = Wd2_2[k * 128 + j]; break;
        case 6: if (k < 128) v = Wd2_3[k * 129 + (j + 1)]; break;  // rotated
        case 7: if (k < 24) v = Wc_0[k * 128 + j];
                else if (k >= 32 && k < 160) v = Wc_0[(k - 8) * 128 + j];
                break;
    }
    g_w[e] = __float2half_rn(v);
}

// ---- helpers ----
__device__ __forceinline__ void mma16816(float* d, const uint32_t* a, const uint32_t* b) {
    asm volatile(
        "mma.sync.aligned.m16n8k16.row.col.f32.f16.f16.f32 "
        "{%0,%1,%2,%3}, {%4,%5,%6,%7}, {%8,%9}, {%0,%1,%2,%3};"
        : "+f"(d[0]), "+f"(d[1]), "+f"(d[2]), "+f"(d[3])
        : "r"(a[0]), "r"(a[1]), "r"(a[2]), "r"(a[3]), "r"(b[0]), "r"(b[1]));
}

__device__ __forceinline__ void ldsm4(uint32_t* r, uint32_t addr) {
    asm volatile("ldmatrix.sync.aligned.m8n8.x4.shared.b16 {%0,%1,%2,%3}, [%4];"
                 : "=r"(r[0]), "=r"(r[1]), "=r"(r[2]), "=r"(r[3]) : "r"(addr));
}

__device__ __forceinline__ void cpasync16(uint32_t dst, const void* src) {
    asm volatile("cp.async.cg.shared.global [%0], [%1], 16;" :: "r"(dst), "l"(src));
}
#define CP_COMMIT() asm volatile("cp.async.commit_group;")
#define CP_WAIT0()  asm volatile("cp.async.wait_group 0;" ::: "memory")

__device__ __forceinline__ uint32_t smem_u32(const void* p) {
    uint32_t a;
    asm("{ .reg .u64 t; cvta.to.shared.u64 t, %1; cvt.u32.u64 %0, t; }" : "=r"(a) : "l"(p));
    return a;
}

__device__ __forceinline__ uint32_t packHi(float f0, float f1) {
    __half h0 = __float2half_rn(f0), h1 = __float2half_rn(f1);
    return ((uint32_t)__half_as_ushort(h1) << 16) | __half_as_ushort(h0);
}

__device__ __forceinline__ void encStore(char* sm, int row, int col, float f0, float f1) {
    *reinterpret_cast<uint32_t*>(sm + EHI_OFF + row * SE + col * 2) = packHi(f0, f1);
}

__device__ __forceinline__ void copyB_async(uint32_t sb, int l) {
    const int n16 = c_n16[l];
    const char* src = reinterpret_cast<const char*>(g_w + c_loff[l]);
    const uint32_t dst = sb + B_OFF;
    for (int i = threadIdx.x; i < n16; i += BLOCK)
        cpasync16(dst + i * 16, src + i * 16);
    CP_COMMIT();
}

// One layer: EK enc k-tiles + AK act k-tiles, weight row stride SB bytes.
// 8 warps, warp tile 32 rows x 64 cols: wm = w&3 (rows 32wm..+31), wg = w>>2
// (cols 64wg..+63). 1-pass fp16: D = A*B (6 LDSM / 16 HMMA per kt).
// After the mid-barrier (all reads done), the next layer's weight copy starts.
template<int EK, int AK, int SB>
__device__ __noinline__ void layerT(char* sm, uint32_t sb, int flags, int nextL) {
    const int t = threadIdx.x;
    const int w = t >> 5, lane = t & 31;
    const int wm = w & 3, wg = w >> 2;
    const int q = lane & 3, rh = lane >> 2;
    const int arow = lane & 15, asel = lane >> 4;
    const int brow = (lane & 7) + ((lane >> 4) << 3);
    const int bsel = (lane >> 3) & 1;
    constexpr int TOT = EK + AK;

    const uint32_t aHi = sb + AHI_OFF + (uint32_t)(32 * wm + arow) * SA + asel * 16;
    const uint32_t eHi = sb + EHI_OFF + (uint32_t)(32 * wm + arow) * SE + asel * 16;
    const uint32_t bB0 = sb + B_OFF + (uint32_t)(brow + wg * 64) * SB + bsel * 16;

    float d[2][8][4];
#pragma unroll
    for (int mt = 0; mt < 2; mt++)
#pragma unroll
        for (int nt = 0; nt < 8; nt++) {
            d[mt][nt][0] = 0.f; d[mt][nt][1] = 0.f;
            d[mt][nt][2] = 0.f; d[mt][nt][3] = 0.f;
        }

#pragma unroll
    for (int kt = 0; kt < TOT; kt++) {
        uint32_t ah[2][4], bf[4][4];
        if (kt < EK) {
            ldsm4(ah[0], eHi + kt * 32);
            ldsm4(ah[1], eHi + 16 * SE + kt * 32);
        } else {
            ldsm4(ah[0], aHi + (kt - EK) * 32);
            ldsm4(ah[1], aHi + 16 * SA + (kt - EK) * 32);
        }
#pragma unroll
        for (int n4 = 0; n4 < 4; n4++)
            ldsm4(bf[n4], bB0 + kt * 32 + n4 * (16 * SB));
#pragma unroll
        for (int n4 = 0; n4 < 4; n4++)
#pragma unroll
            for (int mt = 0; mt < 2; mt++) {
                mma16816(d[mt][2 * n4],     ah[mt], bf[n4]);
                mma16816(d[mt][2 * n4 + 1], ah[mt], bf[n4] + 2);
            }
    }

    // ---- pre-barrier epilogue: relu, aux partials, pack into dead accum regs ----
    const bool relu  = flags & F_RELU;
    const bool store = flags & F_STORE;
    const float* wc1  = reinterpret_cast<const float*>(sm + WC1_OFF);
    const float* bcol = reinterpret_cast<const float*>(sm + BCOL_OFF);

#pragma unroll
    for (int mt = 0; mt < 2; mt++) {
        const int r0 = 32 * wm + 16 * mt + rh;
        if ((flags & F_DENS) && wg == 0 && q == 0) {
            reinterpret_cast<float*>(sm + DENS_OFF)[r0]     = d[mt][0][0];
            reinterpret_cast<float*>(sm + DENS_OFF)[r0 + 8] = d[mt][0][2];
        }
        float b0 = 0.f, b1 = 0.f;
        float g00 = 0.f, g01 = 0.f, g02 = 0.f, g10 = 0.f, g11 = 0.f, g12 = 0.f;
#pragma unroll
        for (int nt = 0; nt < 8; nt++) {
            float f00 = d[mt][nt][0], f01 = d[mt][nt][1];
            float f10 = d[mt][nt][2], f11 = d[mt][nt][3];
            if (relu) {
                f00 = fmaxf(f00, 0.f); f01 = fmaxf(f01, 0.f);
                f10 = fmaxf(f10, 0.f); f11 = fmaxf(f11, 0.f);
            }
            const int c = wg * 64 + nt * 8 + 2 * q;
            if (flags & F_BLEND) {
                b0 = fmaf(f00, bcol[c], fmaf(f01, bcol[c + 1], b0));
                b1 = fmaf(f10, bcol[c], fmaf(f11, bcol[c + 1], b1));
            }
            if (flags & F_RGB) {
                g00 = fmaf(f00, wc1[c * 3 + 0], fmaf(f01, wc1[(c + 1) * 3 + 0], g00));
                g01 = fmaf(f00, wc1[c * 3 + 1], fmaf(f01, wc1[(c + 1) * 3 + 1], g01));
                g02 = fmaf(f00, wc1[c * 3 + 2], fmaf(f01, wc1[(c + 1) * 3 + 2], g02));
                g10 = fmaf(f10, wc1[c * 3 + 0], fmaf(f11, wc1[(c + 1) * 3 + 0], g10));
                g11 = fmaf(f10, wc1[c * 3 + 1], fmaf(f11, wc1[(c + 1) * 3 + 1], g11));
                g12 = fmaf(f10, wc1[c * 3 + 2], fmaf(f11, wc1[(c + 1) * 3 + 2], g12));
            }
            if (store) {
                d[mt][nt][0] = __uint_as_float(packHi(f00, f01));  // row r0
                d[mt][nt][1] = __uint_as_float(packHi(f10, f11));  // row r0+8
            }
        }
        if (flags & F_BLEND) {
            b0 += __shfl_xor_sync(0xffffffffu, b0, 1);
            b0 += __shfl_xor_sync(0xffffffffu, b0, 2);
            b1 += __shfl_xor_sync(0xffffffffu, b1, 1);
            b1 += __shfl_xor_sync(0xffffffffu, b1, 2);
            if (q == 0) {
                reinterpret_cast<float*>(sm + PB_OFF)[wg * 128 + r0]     = b0;
                reinterpret_cast<float*>(sm + PB_OFF)[wg * 128 + r0 + 8] = b1;
            }
        }
        if (flags & F_RGB) {
            g00 += __shfl_xor_sync(0xffffffffu, g00, 1); g00 += __shfl_xor_sync(0xffffffffu, g00, 2);
            g01 += __shfl_xor_sync(0xffffffffu, g01, 1); g01 += __shfl_xor_sync(0xffffffffu, g01, 2);
            g02 += __shfl_xor_sync(0xffffffffu, g02, 1); g02 += __shfl_xor_sync(0xffffffffu, g02, 2);
            g10 += __shfl_xor_sync(0xffffffffu, g10, 1); g10 += __shfl_xor_sync(0xffffffffu, g10, 2);
            g11 += __shfl_xor_sync(0xffffffffu, g11, 1); g11 += __shfl_xor_sync(0xffffffffu, g11, 2);
            g12 += __shfl_xor_sync(0xffffffffu, g12, 1); g12 += __shfl_xor_sync(0xffffffffu, g12, 2);
            if (q == 0) {
                float* pr = reinterpret_cast<float*>(sm + PR_OFF) + (wg * 128) * 3;
                pr[r0 * 3 + 0] = g00; pr[r0 * 3 + 1] = g01; pr[r0 * 3 + 2] = g02;
                pr[(r0 + 8) * 3 + 0] = g10; pr[(r0 + 8) * 3 + 1] = g11; pr[(r0 + 8) * 3 + 2] = g12;
            }
        }
    }

    // All mainloop reads (act + enc + B) complete block-wide.
    __syncthreads();

    // B buffer is now dead -> start next layer's weight copy under the stores.
    if (nextL >= 0) copyB_async(sb, nextL);

    if (store) {
#pragma unroll
        for (int mt = 0; mt < 2; mt++) {
            const int r0 = 32 * wm + 16 * mt + rh;
#pragma unroll
            for (int nt = 0; nt < 8; nt++) {
                char* p = sm + AHI_OFF + (uint32_t)r0 * SA + wg * 128 + nt * 16 + q * 4;
                *reinterpret_cast<uint32_t*>(p)          = __float_as_uint(d[mt][nt][0]);
                *reinterpret_cast<uint32_t*>(p + 8 * SA) = __float_as_uint(d[mt][nt][1]);
            }
        }
    }
}

__global__ void __launch_bounds__(BLOCK, 2)
nerf_mma_kernel(const float* __restrict__ x, const float* __restrict__ Wd2_3,
                const float* __restrict__ Wc_1, float* __restrict__ out, int N) {
    extern __shared__ char sm[];
    const uint32_t sb = smem_u32(sm);
    const int t = threadIdx.x;
    const int i0 = blockIdx.x * PTS;

    copyB_async(sb, 0);

    for (int idx = t; idx < 384; idx += BLOCK)
        reinterpret_cast<float*>(sm + WC1_OFF)[idx] = Wc_1[idx];
    if (t < 128) reinterpret_cast<float*>(sm + BCOL_OFF)[t] = Wd2_3[t * 129];

    float vx = 0.f, vy = 0.f, vz = 0.f;
    if (t < PTS) {
        int i = i0 + t;
        float p0 = 0.f, p1 = 0.f, p2 = 0.f;
        if (i < N) {
            const float* xp = x + 6 * i;
            p0 = xp[0]; p1 = xp[1]; p2 = xp[2];
            vx = xp[3]; vy = xp[4]; vz = xp[5];
        }
#pragma unroll
        for (int dd = 0; dd < 3; dd++) {
            float base = (dd == 0) ? p0 : ((dd == 1) ? p1 : p2);
#pragma unroll
            for (int f = 0; f < 10; f++) {
                float s, c;
                sincosf(base * (CUDART_PI_F * (float)(1 << f)), &s, &c);
                encStore(sm, t, dd * 20 + 2 * f, s, c);
            }
        }
        encStore(sm, t, 60, 0.f, 0.f);
        encStore(sm, t, 62, 0.f, 0.f);
    }

    CP_WAIT0(); __syncthreads();
    layerT<4, 0, 144>(sm, sb, F_RELU | F_STORE, 1);              // L1

    CP_WAIT0(); __syncthreads();
    layerT<0, 8, 272>(sm, sb, F_RELU | F_STORE, 2);              // L2

    CP_WAIT0(); __syncthreads();
    layerT<0, 8, 272>(sm, sb, F_STORE, 3);                       // L3 (linear)

    CP_WAIT0(); __syncthreads();
    layerT<4, 8, 400>(sm, sb, F_RELU | F_STORE, 4);              // L4

    // enc_pos reads finished at L4's mid-barrier -> write view enc now
    if (t < PTS) {
#pragma unroll
        for (int dd = 0; dd < 3; dd++) {
            float base = (dd == 0) ? vx : ((dd == 1) ? vy : vz);
#pragma unroll
            for (int f = 0; f < 4; f++) {
                float s, c;
                sincosf(base * (CUDART_PI_F * (float)(1 << f)), &s, &c);
                encStore(sm, t, dd * 8 + 2 * f, s, c);
            }
        }
        encStore(sm, t, 24, 0.f, 0.f);
        encStore(sm, t, 26, 0.f, 0.f);
        encStore(sm, t, 28, 0.f, 0.f);
        encStore(sm, t, 30, 0.f, 0.f);
    }

    CP_WAIT0(); __syncthreads();
    layerT<0, 8, 272>(sm, sb, F_RELU | F_STORE, 5);              // L5

    CP_WAIT0(); __syncthreads();
    layerT<0, 8, 272>(sm, sb, F_RELU | F_STORE | F_BLEND, 6);    // L6

    CP_WAIT0(); __syncthreads();
    layerT<0, 8, 272>(sm, sb, F_STORE | F_DENS, 7);              // L7 (linear)

    CP_WAIT0(); __syncthreads();
    layerT<2, 8, 336>(sm, sb, F_RELU | F_RGB, -1);               // L8

    __syncthreads();
    if (t < PTS) {
        int i = i0 + t;
        if (i < N) {
            const float* pr = reinterpret_cast<const float*>(sm + PR_OFF);
            const float* pb = reinterpret_cast<const float*>(sm + PB_OFF);
            float braw = pb[t] + pb[128 + t];
            float* o = out + 5 * i;
            o[0] = pr[t * 3 + 0] + pr[(128 + t) * 3 + 0];
            o[1] = pr[t * 3 + 1] + pr[(128 + t) * 3 + 1];
            o[2] = pr[t * 3 + 2] + pr[(128 + t) * 3 + 2];
            o[3] = reinterpret_cast<const float*>(sm + DENS_OFF)[t];
            o[4] = 1.f / (1.f + expf(-braw));
        }
    }
}

extern "C" void kernel_launch(void* const* d_in, const int* in_sizes, int n_in,
                              void* d_out, int out_size) {
    const float* x     = (const float*)d_in[0];
    const float* Wd1_0 = (const float*)d_in[1];
    const float* Wd1_1 = (const float*)d_in[2];
    const float* Wd1_2 = (const float*)d_in[3];
    const float* Wd2_0 = (const float*)d_in[4];
    const float* Wd2_1 = (const float*)d_in[5];
    const float* Wd2_2 = (const float*)d_in[6];
    const float* Wd2_3 = (const float*)d_in[7];
    const float* Wc_0  = (const float*)d_in[8];
    const float* Wc_1  = (const float*)d_in[9];
    float* out = (float*)d_out;

    int N = in_sizes[0] / 6;
    if (N <= 0) return;

    prepass_kernel<<<(143360 + 255) / 256, 256>>>(Wd1_0, Wd1_1, Wd1_2, Wd2_0,
                                                  Wd2_1, Wd2_2, Wd2_3, Wc_0);

    cudaFuncSetAttribute(nerf_mma_kernel,
                         cudaFuncAttributeMaxDynamicSharedMemorySize, SMEM_BYTES);
    int grid = (N + PTS - 1) / PTS;
    nerf_mma_kernel<<<grid, BLOCK, SMEM_BYTES>>>(x, Wd2_3, Wc_1, out, N);
}

// round 17
// speedup vs baseline: 2.1826x; 1.0092x over previous
#include <cuda_runtime.h>
#include <cuda_fp16.h>
#include <math_constants.h>
#include <cstdint>

#define BLOCK 256
#define PTS   128

// ---- smem byte offsets (per block; 2 blocks/SM) ----
#define AHI_OFF   0         // act fp16 [128][136] (stride 272B) = 34816
#define EHI_OFF   34816     // enc fp16 [128][72]  (stride 144B) = 18432
#define B_OFF     53248     // weight buffer (fp16, max 200*128*2=51200)
#define WC1_OFF   104448    // Wc_1 fp32 [128][3]
#define BCOL_OFF  105984    // Wd2_3 col0 fp32 [128]
#define DENS_OFF  106496    // density fp32 [128]
#define PB_OFF    107008    // blend partials fp32 [2][128]
#define PR_OFF    108032    // rgb partials fp32 [2][128][3]
#define SMEM_BYTES 111104

#define SA 272
#define SE 144

// epilogue flag bits
#define F_RELU  1
#define F_STORE 2
#define F_DENS  4
#define F_BLEND 8
#define F_RGB   16

// ---- pre-converted weights: Bt[j][k] row-major, padded, single fp16 plane ----
__device__ __half g_w[143360];

__constant__ int c_loff[9] = {0, 9216, 26624, 44032, 69632, 87040, 104448, 121856, 143360};
__constant__ int c_kpad[8] = {72, 136, 136, 200, 136, 136, 136, 168};
__constant__ int c_n16[8]  = {1152, 2176, 2176, 3200, 2176, 2176, 2176, 2688};

__global__ void prepass_kernel(const float* __restrict__ Wd1_0, const float* __restrict__ Wd1_1,
                               const float* __restrict__ Wd1_2, const float* __restrict__ Wd2_0,
                               const float* __restrict__ Wd2_1, const float* __restrict__ Wd2_2,
                               const float* __restrict__ Wd2_3, const float* __restrict__ Wc_0) {
    int e = blockIdx.x * blockDim.x + threadIdx.x;
    if (e >= 143360) return;
    int l = 0;
    while (e >= c_loff[l + 1]) l++;
    int r = e - c_loff[l];
    int kp = c_kpad[l];
    int j = r / kp;
    int k = r % kp;
    float v = 0.f;
    switch (l) {
        case 0: if (k < 60) v = Wd1_0[k * 128 + j]; break;
        case 1: if (k < 128) v = Wd1_1[k * 128 + j]; break;
        case 2: if (k < 128) v = Wd1_2[k * 128 + j]; break;
        case 3: if (k < 60) v = Wd2_0[k * 128 + j];
                else if (k >= 64 && k < 192) v = Wd2_0[(k - 4) * 128 + j];
                break;
        case 4: if (k < 128) v = Wd2_1[k * 128 + j]; break;
        case 5: if (k < 128) v = Wd2_2[k * 128 + j]; break;
        case 6: if (k < 128) v = Wd2_3[k * 129 + (j + 1)]; break;  // rotated
        case 7: if (k < 24) v = Wc_0[k * 128 + j];
                else if (k >= 32 && k < 160) v = Wc_0[(k - 8) * 128 + j];
                break;
    }
    g_w[e] = __float2half_rn(v);
}

// ---- helpers ----
__device__ __forceinline__ void mma16816(float* d, const uint32_t* a, const uint32_t* b) {
    asm volatile(
        "mma.sync.aligned.m16n8k16.row.col.f32.f16.f16.f32 "
        "{%0,%1,%2,%3}, {%4,%5,%6,%7}, {%8,%9}, {%0,%1,%2,%3};"
        : "+f"(d[0]), "+f"(d[1]), "+f"(d[2]), "+f"(d[3])
        : "r"(a[0]), "r"(a[1]), "r"(a[2]), "r"(a[3]), "r"(b[0]), "r"(b[1]));
}

__device__ __forceinline__ void ldsm4(uint32_t* r, uint32_t addr) {
    asm volatile("ldmatrix.sync.aligned.m8n8.x4.shared.b16 {%0,%1,%2,%3}, [%4];"
                 : "=r"(r[0]), "=r"(r[1]), "=r"(r[2]), "=r"(r[3]) : "r"(addr));
}

__device__ __forceinline__ void stsm4(uint32_t addr, uint32_t r0, uint32_t r1,
                                      uint32_t r2, uint32_t r3) {
    asm volatile("stmatrix.sync.aligned.m8n8.x4.shared.b16 [%0], {%1,%2,%3,%4};"
                 :: "r"(addr), "r"(r0), "r"(r1), "r"(r2), "r"(r3) : "memory");
}

__device__ __forceinline__ void cpasync16(uint32_t dst, const void* src) {
    asm volatile("cp.async.cg.shared.global [%0], [%1], 16;" :: "r"(dst), "l"(src));
}
#define CP_COMMIT() asm volatile("cp.async.commit_group;")
#define CP_WAIT0()  asm volatile("cp.async.wait_group 0;" ::: "memory")

__device__ __forceinline__ uint32_t smem_u32(const void* p) {
    uint32_t a;
    asm("{ .reg .u64 t; cvta.to.shared.u64 t, %1; cvt.u32.u64 %0, t; }" : "=r"(a) : "l"(p));
    return a;
}

__device__ __forceinline__ uint32_t packHi(float f0, float f1) {
    __half h0 = __float2half_rn(f0), h1 = __float2half_rn(f1);
    return ((uint32_t)__half_as_ushort(h1) << 16) | __half_as_ushort(h0);
}

__device__ __forceinline__ void encStore(char* sm, int row, int col, float f0, float f1) {
    *reinterpret_cast<uint32_t*>(sm + EHI_OFF + row * SE + col * 2) = packHi(f0, f1);
}

__device__ __forceinline__ void copyB_async(uint32_t sb, int l) {
    const int n16 = c_n16[l];
    const char* src = reinterpret_cast<const char*>(g_w + c_loff[l]);
    const uint32_t dst = sb + B_OFF;
    for (int i = threadIdx.x; i < n16; i += BLOCK)
        cpasync16(dst + i * 16, src + i * 16);
    CP_COMMIT();
}

// One layer: EK enc k-tiles + AK act k-tiles, weight row stride SB bytes.
// 8 warps, warp tile 32 rows x 64 cols: wm = w&3 (rows 32wm..+31), wg = w>>2
// (cols 64wg..+63). 1-pass fp16: D = A*B (6 LDSM / 16 HMMA per kt).
// Epilogue act stores use stmatrix.x4 (packed D-fragment layout matches).
template<int EK, int AK, int SB>
__device__ __noinline__ void layerT(char* sm, uint32_t sb, int flags, int nextL) {
    const int t = threadIdx.x;
    const int w = t >> 5, lane = t & 31;
    const int wm = w & 3, wg = w >> 2;
    const int q = lane & 3, rh = lane >> 2;
    const int arow = lane & 15, asel = lane >> 4;
    const int brow = (lane & 7) + ((lane >> 4) << 3);
    const int bsel = (lane >> 3) & 1;
    constexpr int TOT = EK + AK;

    const uint32_t aHi = sb + AHI_OFF + (uint32_t)(32 * wm + arow) * SA + asel * 16;
    const uint32_t eHi = sb + EHI_OFF + (uint32_t)(32 * wm + arow) * SE + asel * 16;
    const uint32_t bB0 = sb + B_OFF + (uint32_t)(brow + wg * 64) * SB + bsel * 16;

    float d[2][8][4];
#pragma unroll
    for (int mt = 0; mt < 2; mt++)
#pragma unroll
        for (int nt = 0; nt < 8; nt++) {
            d[mt][nt][0] = 0.f; d[mt][nt][1] = 0.f;
            d[mt][nt][2] = 0.f; d[mt][nt][3] = 0.f;
        }

#pragma unroll
    for (int kt = 0; kt < TOT; kt++) {
        uint32_t ah[2][4], bf[4][4];
        if (kt < EK) {
            ldsm4(ah[0], eHi + kt * 32);
            ldsm4(ah[1], eHi + 16 * SE + kt * 32);
        } else {
            ldsm4(ah[0], aHi + (kt - EK) * 32);
            ldsm4(ah[1], aHi + 16 * SA + (kt - EK) * 32);
        }
#pragma unroll
        for (int n4 = 0; n4 < 4; n4++)
            ldsm4(bf[n4], bB0 + kt * 32 + n4 * (16 * SB));
#pragma unroll
        for (int n4 = 0; n4 < 4; n4++)
#pragma unroll
            for (int mt = 0; mt < 2; mt++) {
                mma16816(d[mt][2 * n4],     ah[mt], bf[n4]);
                mma16816(d[mt][2 * n4 + 1], ah[mt], bf[n4] + 2);
            }
    }

    // ---- pre-barrier epilogue: relu, aux partials, pack into dead accum regs ----
    const bool relu  = flags & F_RELU;
    const bool store = flags & F_STORE;
    const float* wc1  = reinterpret_cast<const float*>(sm + WC1_OFF);
    const float* bcol = reinterpret_cast<const float*>(sm + BCOL_OFF);

#pragma unroll
    for (int mt = 0; mt < 2; mt++) {
        const int r0 = 32 * wm + 16 * mt + rh;
        if ((flags & F_DENS) && wg == 0 && q == 0) {
            reinterpret_cast<float*>(sm + DENS_OFF)[r0]     = d[mt][0][0];
            reinterpret_cast<float*>(sm + DENS_OFF)[r0 + 8] = d[mt][0][2];
        }
        float b0 = 0.f, b1 = 0.f;
        float g00 = 0.f, g01 = 0.f, g02 = 0.f, g10 = 0.f, g11 = 0.f, g12 = 0.f;
#pragma unroll
        for (int nt = 0; nt < 8; nt++) {
            float f00 = d[mt][nt][0], f01 = d[mt][nt][1];
            float f10 = d[mt][nt][2], f11 = d[mt][nt][3];
            if (relu) {
                f00 = fmaxf(f00, 0.f); f01 = fmaxf(f01, 0.f);
                f10 = fmaxf(f10, 0.f); f11 = fmaxf(f11, 0.f);
            }
            const int c = wg * 64 + nt * 8 + 2 * q;
            if (flags & F_BLEND) {
                b0 = fmaf(f00, bcol[c], fmaf(f01, bcol[c + 1], b0));
                b1 = fmaf(f10, bcol[c], fmaf(f11, bcol[c + 1], b1));
            }
            if (flags & F_RGB) {
                g00 = fmaf(f00, wc1[c * 3 + 0], fmaf(f01, wc1[(c + 1) * 3 + 0], g00));
                g01 = fmaf(f00, wc1[c * 3 + 1], fmaf(f01, wc1[(c + 1) * 3 + 1], g01));
                g02 = fmaf(f00, wc1[c * 3 + 2], fmaf(f01, wc1[(c + 1) * 3 + 2], g02));
                g10 = fmaf(f10, wc1[c * 3 + 0], fmaf(f11, wc1[(c + 1) * 3 + 0], g10));
                g11 = fmaf(f10, wc1[c * 3 + 1], fmaf(f11, wc1[(c + 1) * 3 + 1], g11));
                g12 = fmaf(f10, wc1[c * 3 + 2], fmaf(f11, wc1[(c + 1) * 3 + 2], g12));
            }
            if (store) {
                d[mt][nt][0] = __uint_as_float(packHi(f00, f01));  // strip h=0 (rows r0-blk)
                d[mt][nt][1] = __uint_as_float(packHi(f10, f11));  // strip h=1 (rows +8)
            }
        }
        if (flags & F_BLEND) {
            b0 += __shfl_xor_sync(0xffffffffu, b0, 1);
            b0 += __shfl_xor_sync(0xffffffffu, b0, 2);
            b1 += __shfl_xor_sync(0xffffffffu, b1, 1);
            b1 += __shfl_xor_sync(0xffffffffu, b1, 2);
            if (q == 0) {
                reinterpret_cast<float*>(sm + PB_OFF)[wg * 128 + r0]     = b0;
                reinterpret_cast<float*>(sm + PB_OFF)[wg * 128 + r0 + 8] = b1;
            }
        }
        if (flags & F_RGB) {
            g00 += __shfl_xor_sync(0xffffffffu, g00, 1); g00 += __shfl_xor_sync(0xffffffffu, g00, 2);
            g01 += __shfl_xor_sync(0xffffffffu, g01, 1); g01 += __shfl_xor_sync(0xffffffffu, g01, 2);
            g02 += __shfl_xor_sync(0xffffffffu, g02, 1); g02 += __shfl_xor_sync(0xffffffffu, g02, 2);
            g10 += __shfl_xor_sync(0xffffffffu, g10, 1); g10 += __shfl_xor_sync(0xffffffffu, g10, 2);
            g11 += __shfl_xor_sync(0xffffffffu, g11, 1); g11 += __shfl_xor_sync(0xffffffffu, g11, 2);
            g12 += __shfl_xor_sync(0xffffffffu, g12, 1); g12 += __shfl_xor_sync(0xffffffffu, g12, 2);
            if (q == 0) {
                float* pr = reinterpret_cast<float*>(sm + PR_OFF) + (wg * 128) * 3;
                pr[r0 * 3 + 0] = g00; pr[r0 * 3 + 1] = g01; pr[r0 * 3 + 2] = g02;
                pr[(r0 + 8) * 3 + 0] = g10; pr[(r0 + 8) * 3 + 1] = g11; pr[(r0 + 8) * 3 + 2] = g12;
            }
        }
    }

    // Block-wide: all mainloop reads done before act overwritten / B recopied.
    // L8 (no store, no next copy) skips it — kernel-level sync follows anyway.
    if (store || nextL >= 0) __syncthreads();

    // B buffer is now dead -> start next layer's weight copy under the stores.
    if (nextL >= 0) copyB_async(sb, nextL);

    if (store) {
        // stmatrix.x4: 4 row-strips (8 rows each) x 2 col-groups (32 cols each).
        // Lane L: row-in-strip = L&7, tile-in-group = L>>3.
        const uint32_t sbase = sb + AHI_OFF +
            (uint32_t)(32 * wm + (lane & 7)) * SA + (wg * 64 + 8 * (lane >> 3)) * 2;
#pragma unroll
        for (int s = 0; s < 4; s++) {
            const int mt = s >> 1, h = s & 1;
            const uint32_t a = sbase + s * (8 * SA);
            stsm4(a, __float_as_uint(d[mt][0][h]), __float_as_uint(d[mt][1][h]),
                     __float_as_uint(d[mt][2][h]), __float_as_uint(d[mt][3][h]));
            stsm4(a + 64, __float_as_uint(d[mt][4][h]), __float_as_uint(d[mt][5][h]),
                          __float_as_uint(d[mt][6][h]), __float_as_uint(d[mt][7][h]));
        }
    }
}

__global__ void __launch_bounds__(BLOCK, 2)
nerf_mma_kernel(const float* __restrict__ x, const float* __restrict__ Wd2_3,
                const float* __restrict__ Wc_1, float* __restrict__ out, int N) {
    extern __shared__ char sm[];
    const uint32_t sb = smem_u32(sm);
    const int t = threadIdx.x;
    const int i0 = blockIdx.x * PTS;

    copyB_async(sb, 0);

    for (int idx = t; idx < 384; idx += BLOCK)
        reinterpret_cast<float*>(sm + WC1_OFF)[idx] = Wc_1[idx];
    if (t < 128) reinterpret_cast<float*>(sm + BCOL_OFF)[t] = Wd2_3[t * 129];

    float vx = 0.f, vy = 0.f, vz = 0.f;
    if (t < PTS) {
        int i = i0 + t;
        float p0 = 0.f, p1 = 0.f, p2 = 0.f;
        if (i < N) {
            const float* xp = x + 6 * i;
            p0 = xp[0]; p1 = xp[1]; p2 = xp[2];
            vx = xp[3]; vy = xp[4]; vz = xp[5];
        }
#pragma unroll
        for (int dd = 0; dd < 3; dd++) {
            float base = (dd == 0) ? p0 : ((dd == 1) ? p1 : p2);
#pragma unroll
            for (int f = 0; f < 10; f++) {
                float s, c;
                sincosf(base * (CUDART_PI_F * (float)(1 << f)), &s, &c);
                encStore(sm, t, dd * 20 + 2 * f, s, c);
            }
        }
        encStore(sm, t, 60, 0.f, 0.f);
        encStore(sm, t, 62, 0.f, 0.f);
    }

    CP_WAIT0(); __syncthreads();
    layerT<4, 0, 144>(sm, sb, F_RELU | F_STORE, 1);              // L1

    CP_WAIT0(); __syncthreads();
    layerT<0, 8, 272>(sm, sb, F_RELU | F_STORE, 2);              // L2

    CP_WAIT0(); __syncthreads();
    layerT<0, 8, 272>(sm, sb, F_STORE, 3);                       // L3 (linear)

    CP_WAIT0(); __syncthreads();
    layerT<4, 8, 400>(sm, sb, F_RELU | F_STORE, 4);              // L4

    // enc_pos reads finished at L4's mid-barrier -> write view enc now
    if (t < PTS) {
#pragma unroll
        for (int dd = 0; dd < 3; dd++) {
            float base = (dd == 0) ? vx : ((dd == 1) ? vy : vz);
#pragma unroll
            for (int f = 0; f < 4; f++) {
                float s, c;
                sincosf(base * (CUDART_PI_F * (float)(1 << f)), &s, &c);
                encStore(sm, t, dd * 8 + 2 * f, s, c);
            }
        }
        encStore(sm, t, 24, 0.f, 0.f);
        encStore(sm, t, 26, 0.f, 0.f);
        encStore(sm, t, 28, 0.f, 0.f);
        encStore(sm, t, 30, 0.f, 0.f);
    }

    CP_WAIT0(); __syncthreads();
    layerT<0, 8, 272>(sm, sb, F_RELU | F_STORE, 5);              // L5

    CP_WAIT0(); __syncthreads();
    layerT<0, 8, 272>(sm, sb, F_RELU | F_STORE | F_BLEND, 6);    // L6

    CP_WAIT0(); __syncthreads();
    layerT<0, 8, 272>(sm, sb, F_STORE | F_DENS, 7);              // L7 (linear)

    CP_WAIT0(); __syncthreads();
    layerT<2, 8, 336>(sm, sb, F_RELU | F_RGB, -1);               // L8

    __syncthreads();
    if (t < PTS) {
        int i = i0 + t;
        if (i < N) {
            const float* pr = reinterpret_cast<const float*>(sm + PR_OFF);
            const float* pb = reinterpret_cast<const float*>(sm + PB_OFF);
            float braw = pb[t] + pb[128 + t];
            float* o = out + 5 * i;
            o[0] = pr[t * 3 + 0] + pr[(128 + t) * 3 + 0];
            o[1] = pr[t * 3 + 1] + pr[(128 + t) * 3 + 1];
            o[2] = pr[t * 3 + 2] + pr[(128 + t) * 3 + 2];
            o[3] = reinterpret_cast<const float*>(sm + DENS_OFF)[t];
            o[4] = 1.f / (1.f + expf(-braw));
        }
    }
}

extern "C" void kernel_launch(void* const* d_in, const int* in_sizes, int n_in,
                              void* d_out, int out_size) {
    const float* x     = (const float*)d_in[0];
    const float* Wd1_0 = (const float*)d_in[1];
    const float* Wd1_1 = (const float*)d_in[2];
    const float* Wd1_2 = (const float*)d_in[3];
    const float* Wd2_0 = (const float*)d_in[4];
    const float* Wd2_1 = (const float*)d_in[5];
    const float* Wd2_2 = (const float*)d_in[6];
    const float* Wd2_3 = (const float*)d_in[7];
    const float* Wc_0  = (const float*)d_in[8];
    const float* Wc_1  = (const float*)d_in[9];
    float* out = (float*)d_out;

    int N = in_sizes[0] / 6;
    if (N <= 0) return;

    prepass_kernel<<<(143360 + 255) / 256, 256>>>(Wd1_0, Wd1_1, Wd1_2, Wd2_0,
                                                  Wd2_1, Wd2_2, Wd2_3, Wc_0);

    cudaFuncSetAttribute(nerf_mma_kernel,
                         cudaFuncAttributeMaxDynamicSharedMemorySize, SMEM_BYTES);
    int grid = (N + PTS - 1) / PTS;
    nerf_mma_kernel<<<grid, BLOCK, SMEM_BYTES>>>(x, Wd2_3, Wc_1, out, N);
}